// round 9
// baseline (speedup 1.0000x reference)
#include <cuda_runtime.h>
#include <cuda_bf16.h>
#include <cstdint>

// Problem sizes (fixed per reference)
#define BATCH 16384
#define NSETS 1024
#define NCLS  128

// ---------------- device scratch (no allocations allowed) ----------------
__device__ __nv_bfloat16 g_pb[(size_t)BATCH * NSETS];   // clipped p in bf16 (32MB)
__device__ __nv_bfloat16 g_mb[(size_t)NSETS * NSETS];   // moebius in bf16   (2MB)
__device__ float  g_colsum[NSETS];
__device__ double g_acc[3];  // 0: sum log-lik, 1: sum|rowdot-1|, 2: sum relu(-mass)
__device__ int    g_tgt_is64;

// ---------------- PTX helpers (legacy HMMA path; tcgen05 not available:
// harness PTX targets compute_103, arch-accel features need compute_103a) ----
__device__ __forceinline__ void ldm_x4(uint32_t* r, uint32_t addr) {
    asm volatile("ldmatrix.sync.aligned.m8n8.x4.shared.b16 {%0,%1,%2,%3}, [%4];"
                 : "=r"(r[0]), "=r"(r[1]), "=r"(r[2]), "=r"(r[3]) : "r"(addr));
}
__device__ __forceinline__ void mma16816(float* c, const uint32_t* a, uint32_t b0, uint32_t b1) {
    asm volatile("mma.sync.aligned.m16n8k16.row.col.f32.bf16.bf16.f32 "
                 "{%0,%1,%2,%3}, {%4,%5,%6,%7}, {%8,%9}, {%0,%1,%2,%3};"
                 : "+f"(c[0]), "+f"(c[1]), "+f"(c[2]), "+f"(c[3])
                 : "r"(a[0]), "r"(a[1]), "r"(a[2]), "r"(a[3]), "r"(b0), "r"(b1));
}
#define CP_ASYNC16(sa, ga) \
    asm volatile("cp.async.cg.shared.global [%0], [%1], 16;\n" :: "r"(sa), "l"(ga))
#define CP_COMMIT() asm volatile("cp.async.commit_group;\n" ::: "memory")
#define CP_WAIT1()  asm volatile("cp.async.wait_group 1;\n" ::: "memory")

// ---------------- kernels ----------------
// Detect whether the target-index buffer is int64 or int32 (see R4 notes):
// reads the first 128 int32 words (in-bounds either way); int64 => all odd
// (high) words are 0; int32 => odd words ~U[0,128), P(all zero) = 128^-64.
__global__ void detect_tgt(const int* __restrict__ t) {
    int bad = 0;
    #pragma unroll
    for (int i = 0; i < 64; i++) bad |= t[2 * i + 1];
    g_tgt_is64 = (bad == 0) ? 1 : 0;
}

__global__ void init_k() {
    int i = blockIdx.x * 256 + threadIdx.x;
    if (i < NSETS) g_colsum[i] = 0.0f;
    if (i < 3) g_acc[i] = 0.0;
}

// colsum[k] = sum_s M[s,k]; also convert M -> bf16. Grid: 64 blocks x 256 thr.
__global__ void prep_moebius(const float* __restrict__ M) {
    int c = threadIdx.x * 4;
    float4 s = make_float4(0.f, 0.f, 0.f, 0.f);
    int row0 = blockIdx.x * 16;
    #pragma unroll 4
    for (int r = 0; r < 16; r++) {
        int row = row0 + r;
        float4 v = *(const float4*)(M + (size_t)row * NSETS + c);
        s.x += v.x; s.y += v.y; s.z += v.z; s.w += v.w;
        __nv_bfloat162* dst = (__nv_bfloat162*)(g_mb + (size_t)row * NSETS + c);
        dst[0] = __floats2bfloat162_rn(v.x, v.y);
        dst[1] = __floats2bfloat162_rn(v.z, v.w);
    }
    atomicAdd(&g_colsum[c + 0], s.x);
    atomicAdd(&g_colsum[c + 1], s.y);
    atomicAdd(&g_colsum[c + 2], s.z);
    atomicAdd(&g_colsum[c + 3], s.w);
}

// Per-row: clip p, BCE (single-log form: t in {0,1} exactly), rowdot with
// colsum, p->bf16. Grid: 2048 blocks x 256 thr; warp w = row blockIdx.x*8+w.
__global__ __launch_bounds__(256) void bce_ms_pconv(const float* __restrict__ pred,
                                                    const float* __restrict__ memb,
                                                    const void* __restrict__ tgt) {
    int warp = threadIdx.x >> 5, lane = threadIdx.x & 31;
    int row = blockIdx.x * 8 + warp;
    const float4* pr = (const float4*)(pred + (size_t)row * NSETS);
    int cls;
    if (g_tgt_is64) cls = (int)((const long long*)tgt)[row];
    else            cls = ((const int*)tgt)[row];
    cls = min(max(cls, 0), NCLS - 1);   // defensive: wrong -> rel_err, not crash
    const float4* mr = (const float4*)(memb + (size_t)cls * NSETS);
    const float4* cs = (const float4*)g_colsum;

    float bce = 0.f, dot = 0.f;
    #pragma unroll
    for (int it = 0; it < 8; it++) {
        int i = it * 32 + lane;           // float4 index, 0..255
        float4 p = pr[i];
        float4 m = mr[i];
        float4 c = cs[i];
        p.x = fminf(fmaxf(p.x, 1e-7f), 0.9999999f);
        p.y = fminf(fmaxf(p.y, 1e-7f), 0.9999999f);
        p.z = fminf(fmaxf(p.z, 1e-7f), 0.9999999f);
        p.w = fminf(fmaxf(p.w, 1e-7f), 0.9999999f);
        bce += __logf(m.x > 0.5f ? p.x : 1.f - p.x);
        bce += __logf(m.y > 0.5f ? p.y : 1.f - p.y);
        bce += __logf(m.z > 0.5f ? p.z : 1.f - p.z);
        bce += __logf(m.w > 0.5f ? p.w : 1.f - p.w);
        dot += p.x * c.x + p.y * c.y + p.z * c.z + p.w * c.w;
        __nv_bfloat162* dst = (__nv_bfloat162*)(g_pb + (size_t)row * NSETS + (size_t)i * 4);
        dst[0] = __floats2bfloat162_rn(p.x, p.y);
        dst[1] = __floats2bfloat162_rn(p.z, p.w);
    }
    #pragma unroll
    for (int off = 16; off > 0; off >>= 1) {
        bce += __shfl_down_sync(0xffffffffu, bce, off);
        dot += __shfl_down_sync(0xffffffffu, dot, off);
    }
    __shared__ float s_b[8], s_m[8];
    if (lane == 0) { s_b[warp] = bce; s_m[warp] = fabsf(dot - 1.0f); }
    __syncthreads();
    if (threadIdx.x == 0) {
        float b = 0.f, ms = 0.f;
        #pragma unroll
        for (int i = 0; i < 8; i++) { b += s_b[i]; ms += s_m[i]; }
        atomicAdd(&g_acc[0], (double)b);
        atomicAdd(&g_acc[1], (double)ms);
    }
}

// GEMM: masses[b,s] = sum_k pb[b,k] * mb[s,k]  (both K-major, NT)
// CTA tile 128x128, BK=64, 256 threads, 8 warps (4x2), warp tile 32x64.
// Double-buffered cp.async, dynamic smem 72KB, 2 CTAs/SM.
// Grid: blockIdx.x = N tile (8) so a wave covers all N-tiles -> A hits L2 8x.
// Epilogue: sum relu(-acc) -> one atomic per block. Masses never hit memory.
#define BM 128
#define BN 128
#define BK 64
#define LDK 72                      // smem row stride in bf16 (64+8 pad, 144B)
#define STAGE_BYTES (BM * LDK * 2)  // 18432 B per matrix per stage
#define GSMEM_TOTAL (4 * STAGE_BYTES)   // A0,A1,B0,B1 = 73728 B
#define KT  (NSETS / BK)            // 16

__global__ __launch_bounds__(256, 2) void gemm_mr() {
    extern __shared__ char smem[];
    int tid = threadIdx.x;
    int warp = tid >> 5, lane = tid & 31;
    int wm = (warp >> 1) * 32;   // warp M offset (0,32,64,96)
    int wn = (warp & 1) * 64;    // warp N offset (0,64)

    const char* Ag = (const char*)g_pb + (size_t)blockIdx.y * BM * 2048; // 2048B rows
    const char* Bg = (const char*)g_mb + (size_t)blockIdx.x * BN * 2048;

    uint32_t sbase;
    asm("{ .reg .u64 t; cvta.to.shared.u64 t, %1; cvt.u32.u64 %0, t; }"
        : "=r"(sbase) : "l"(smem));
    uint32_t sA[2] = { sbase,                   sbase + STAGE_BYTES };
    uint32_t sB[2] = { sbase + 2 * STAGE_BYTES, sbase + 3 * STAGE_BYTES };

    // thread t loads row r = t>>1, 16B chunks (t&1)*4 .. +3 of both A and B
    int ld_r = tid >> 1;
    int ld_c = (tid & 1) * 4;
    auto load_stage = [&](int st, int kt) {
        const char* ga = Ag + (size_t)ld_r * 2048 + (size_t)kt * 128;
        const char* gb = Bg + (size_t)ld_r * 2048 + (size_t)kt * 128;
        uint32_t soff = (uint32_t)ld_r * 144u + (uint32_t)ld_c * 16u;
        #pragma unroll
        for (int c = 0; c < 4; c++) {
            CP_ASYNC16(sA[st] + soff + c * 16u, ga + (ld_c + c) * 16);
            CP_ASYNC16(sB[st] + soff + c * 16u, gb + (ld_c + c) * 16);
        }
    };

    float acc[2][8][4];
    #pragma unroll
    for (int i = 0; i < 2; i++)
        #pragma unroll
        for (int j = 0; j < 8; j++)
            #pragma unroll
            for (int k = 0; k < 4; k++) acc[i][j][k] = 0.f;

    load_stage(0, 0);
    CP_COMMIT();

    for (int kt = 0; kt < KT; kt++) {
        if (kt + 1 < KT) load_stage((kt + 1) & 1, kt + 1);
        CP_COMMIT();
        CP_WAIT1();
        __syncthreads();

        int st = kt & 1;
        #pragma unroll
        for (int ks = 0; ks < 4; ks++) {
            int kk = ks * 16;
            int c = kk + (lane >> 4) * 8;       // bf16 col within stage
            uint32_t a[2][4], b[4][4];
            #pragma unroll
            for (int mt = 0; mt < 2; mt++) {
                int r = wm + mt * 16 + (lane & 15);
                ldm_x4(a[mt], sA[st] + (uint32_t)r * 144u + (uint32_t)c * 2u);
            }
            #pragma unroll
            for (int bt = 0; bt < 4; bt++) {
                int r = wn + bt * 16 + (lane & 15);
                ldm_x4(b[bt], sB[st] + (uint32_t)r * 144u + (uint32_t)c * 2u);
            }
            #pragma unroll
            for (int mt = 0; mt < 2; mt++)
                #pragma unroll
                for (int bt = 0; bt < 4; bt++) {
                    mma16816(acc[mt][2 * bt + 0], a[mt], b[bt][0], b[bt][2]);
                    mma16816(acc[mt][2 * bt + 1], a[mt], b[bt][1], b[bt][3]);
                }
        }
        __syncthreads();
    }

    // Epilogue: sum relu(-mass) over this block's 128x128 tile (layout-agnostic:
    // every product lands in exactly one acc slot, so the plain sum is exact).
    float part = 0.f;
    #pragma unroll
    for (int i = 0; i < 2; i++)
        #pragma unroll
        for (int j = 0; j < 8; j++)
            #pragma unroll
            for (int k = 0; k < 4; k++) part += fmaxf(-acc[i][j][k], 0.f);
    #pragma unroll
    for (int off = 16; off > 0; off >>= 1)
        part += __shfl_down_sync(0xffffffffu, part, off);
    __shared__ float sp[8];
    if (lane == 0) sp[warp] = part;
    __syncthreads();
    if (tid == 0) {
        float s = 0.f;
        #pragma unroll
        for (int i = 0; i < 8; i++) s += sp[i];
        atomicAdd(&g_acc[2], (double)s);
    }
}

__global__ void finalize_k(float* out, int out_size) {
    double inv_bs = 1.0 / ((double)BATCH * (double)NSETS);
    double bce = -g_acc[0] * inv_bs;
    double ms  = g_acc[1] / (double)BATCH;
    double mr  = g_acc[2] * inv_bs;
    float vals[4];
    vals[0] = (float)(bce + 0.001 * mr + 0.001 * ms);
    vals[1] = (float)bce;
    vals[2] = (float)mr;
    vals[3] = (float)ms;
    for (int i = 0; i < 4 && i < out_size; i++) out[i] = vals[i];
}

// ---------------- launch ----------------
extern "C" void kernel_launch(void* const* d_in, const int* in_sizes, int n_in,
                              void* d_out, int out_size) {
    const float* pred = nullptr;       // 16384*1024
    const float* memb = nullptr;       // 128*1024
    const float* moeb = nullptr;       // 1024*1024
    const void*  tgt  = nullptr;       // 16384 (int32 OR int64 — device-detected)
    for (int i = 0; i < n_in; i++) {
        long long n = in_sizes[i];
        if (n == (long long)BATCH * NSETS) pred = (const float*)d_in[i];
        else if (n == (long long)NCLS * NSETS) memb = (const float*)d_in[i];
        else if (n == (long long)NSETS * NSETS) moeb = (const float*)d_in[i];
        else if (n == (long long)BATCH) tgt = d_in[i];
    }
    if (!pred || !memb || !moeb || !tgt) return;

    static bool attr_done = false;
    if (!attr_done) {
        cudaFuncSetAttribute(gemm_mr, cudaFuncAttributeMaxDynamicSharedMemorySize,
                             GSMEM_TOTAL);
        attr_done = true;
    }

    detect_tgt<<<1, 1>>>((const int*)tgt);
    init_k<<<4, 256>>>();
    prep_moebius<<<64, 256>>>(moeb);
    bce_ms_pconv<<<BATCH / 8, 256>>>(pred, memb, tgt);
    dim3 g(NSETS / BN, BATCH / BM);   // x = N tiles (8), y = M tiles (128)
    gemm_mr<<<g, 256, GSMEM_TOTAL>>>();
    finalize_k<<<1, 1>>>((float*)d_out, out_size);
}